// round 1
// baseline (speedup 1.0000x reference)
#include <cuda_runtime.h>
#include <cuda_bf16.h>

// Problem constants
#define NB   32
#define IC   128
#define H    64
#define W    64
#define OC   256
#define OH   62
#define OW   62

// Tiling
#define CC   8     // input-channel chunk in smem
#define TH   4     // output rows per block
#define TW   32    // output cols per block
#define OCT  64    // output channels per block

__global__ __launch_bounds__(256) void conv2d_fp32_tiled(
    const float* __restrict__ in,
    const float* __restrict__ wt,
    float* __restrict__ out)
{
    // Input patch: CC channels x (TH+2) rows x (TW+2) cols.
    // Row stride 34 -> bank = (2*row + 8*colgroup) mod 32: conflict-free for
    // the 16 distinct (row, colgroup) pairs per warp (2-way broadcast).
    __shared__ float in_s[CC][TH + 2][TW + 2];
    // Weights: [c_local*9 + kpos][oc] with oc innermost -> float4 per thread.
    __shared__ float w_s[CC * 9][OCT];

    const int wt_tile = blockIdx.x;          // 0..1   (cols 0..31 / 32..61)
    const int ht_tile = blockIdx.y;          // 0..15  (4 rows each)
    const int nz      = blockIdx.z;          // 0..127 = n*4 + oc_group
    const int n   = nz >> 2;
    const int oc0 = (nz & 3) * OCT;
    const int h0  = ht_tile * TH;
    const int w0  = wt_tile * TW;

    const int t     = threadIdx.x;
    const int ocg   = t >> 4;                // 0..15: 4 out-channels each
    const int pg    = t & 15;                // 0..15: 8 positions each
    const int prow  = pg >> 2;               // 0..3
    const int pcol0 = (pg & 3) * 8;          // 0,8,16,24

    float acc[4][8];
    #pragma unroll
    for (int i = 0; i < 4; i++)
        #pragma unroll
        for (int j = 0; j < 8; j++)
            acc[i][j] = 0.0f;

    const float* in_n = in + (size_t)n * IC * H * W;

    for (int cc = 0; cc < IC; cc += CC) {
        // ---- stage input patch: CC*(TH+2)*(TW+2) = 1632 floats ----
        for (int idx = t; idx < CC * (TH + 2) * (TW + 2); idx += 256) {
            int c   = idx / ((TH + 2) * (TW + 2));
            int rem = idx % ((TH + 2) * (TW + 2));
            int r   = rem / (TW + 2);
            int col = rem % (TW + 2);
            int gh = h0 + r;
            int gw = w0 + col;
            float v = 0.0f;
            if (gh < H && gw < W)
                v = in_n[(size_t)(cc + c) * H * W + gh * W + gw];
            in_s[c][r][col] = v;
        }
        // ---- stage weights chunk: OCT*CC*9 = 4608 floats ----
        for (int idx = t; idx < OCT * CC * 9; idx += 256) {
            int k  = idx / OCT;              // c_local*9 + kpos
            int oc = idx % OCT;
            int c_local = k / 9;
            int kpos    = k % 9;
            w_s[k][oc] =
                wt[(size_t)(oc0 + oc) * IC * 9 + (size_t)(cc + c_local) * 9 + kpos];
        }
        __syncthreads();

        // ---- compute: rolled over c (I-cache), unrolled over kh/kw ----
        #pragma unroll 1
        for (int c = 0; c < CC; c++) {
            #pragma unroll
            for (int kh = 0; kh < 3; kh++) {
                float a[10];                 // sliding window over kw
                #pragma unroll
                for (int j = 0; j < 10; j++)
                    a[j] = in_s[c][prow + kh][pcol0 + j];
                #pragma unroll
                for (int kw = 0; kw < 3; kw++) {
                    const float4 wv =
                        *(const float4*)&w_s[c * 9 + kh * 3 + kw][ocg * 4];
                    #pragma unroll
                    for (int j = 0; j < 8; j++) {
                        acc[0][j] += wv.x * a[j + kw];
                        acc[1][j] += wv.y * a[j + kw];
                        acc[2][j] += wv.z * a[j + kw];
                        acc[3][j] += wv.w * a[j + kw];
                    }
                }
            }
        }
        __syncthreads();
    }

    // ---- store (guard ragged edges: 62 = 15*4+2 rows, 62 = 32+30 cols) ----
    const int oh = h0 + prow;
    if (oh < OH) {
        #pragma unroll
        for (int i = 0; i < 4; i++) {
            const int oc = oc0 + ocg * 4 + i;
            float* op = out + ((size_t)n * OC + oc) * OH * OW + (size_t)oh * OW;
            #pragma unroll
            for (int j = 0; j < 8; j++) {
                int ow = w0 + pcol0 + j;
                if (ow < OW) op[ow] = acc[i][j];
            }
        }
    }
}

extern "C" void kernel_launch(void* const* d_in, const int* in_sizes, int n_in,
                              void* d_out, int out_size)
{
    const float* in = (const float*)d_in[0];   // [32,128,64,64]
    const float* wt = (const float*)d_in[1];   // [256,128,3,3]
    float* out = (float*)d_out;                // [32,256,62,62]

    dim3 grid(2, 16, NB * (OC / OCT));         // (2, 16, 128)
    conv2d_fp32_tiled<<<grid, 256>>>(in, wt, out);
}

// round 3
// speedup vs baseline: 3.8852x; 3.8852x over previous
#include <cuda_runtime.h>
#include <cstdint>

#define NTHR 512
#define KTOT 1152
#define NCH  36          // K chunks of 32

// smem layout (bytes)
#define A_ROWB 144       // 128B data + 16B pad (conflict-free ldmatrix)
#define B_ROWB 144
#define SM_A0  0                       // 128 rows * 144
#define SM_A1  18432
#define SM_B0  36864                   // 256 rows * 144
#define SM_B1  73728
#define SM_OFF 110592                  // 1152 int offsets
#define SM_TOT 115200
#define EPI_LD 132                     // epilogue [128 oc][132 m] floats

__device__ __forceinline__ uint32_t s2u(const void* p) {
    uint32_t a;
    asm("{ .reg .u64 t; cvta.to.shared.u64 t, %1; cvt.u32.u64 %0, t; }" : "=r"(a) : "l"(p));
    return a;
}

__device__ __forceinline__ void ldsm4(uint32_t* r, uint32_t addr) {
    asm volatile("ldmatrix.sync.aligned.m8n8.x4.shared.b16 {%0,%1,%2,%3}, [%4];"
        : "=r"(r[0]), "=r"(r[1]), "=r"(r[2]), "=r"(r[3]) : "r"(addr));
}

__device__ __forceinline__ uint32_t f2tf(uint32_t u) {
    uint32_t o; float f = __uint_as_float(u);
    asm("cvt.rna.tf32.f32 %0, %1;" : "=r"(o) : "f"(f));
    return o;
}

__device__ __forceinline__ void mma8(float* d, const uint32_t* a, const uint32_t* b) {
    asm volatile("mma.sync.aligned.m16n8k8.row.col.f32.tf32.tf32.f32 "
        "{%0,%1,%2,%3}, {%4,%5,%6,%7}, {%8,%9}, {%0,%1,%2,%3};"
        : "+f"(d[0]), "+f"(d[1]), "+f"(d[2]), "+f"(d[3])
        : "r"(a[0]), "r"(a[1]), "r"(a[2]), "r"(a[3]), "r"(b[0]), "r"(b[1]));
}

#define CP4(dst, src) \
    asm volatile("cp.async.ca.shared.global [%0], [%1], 4;"  :: "r"(dst), "l"(src) : "memory")
#define CP16(dst, src) \
    asm volatile("cp.async.cg.shared.global [%0], [%1], 16;" :: "r"(dst), "l"(src) : "memory")
#define CP_COMMIT() asm volatile("cp.async.commit_group;" ::: "memory")

__global__ __launch_bounds__(NTHR, 1)
void conv2d_tf32_mmasync(const float* __restrict__ in,
                         const float* __restrict__ wt,
                         float* __restrict__ out)
{
    extern __shared__ char smem[];
    const uint32_t sb = s2u(smem);
    float* smf = (float*)smem;
    int* offs = (int*)(smem + SM_OFF);

    const int tid = threadIdx.x;
    const int wid = tid >> 5, lane = tid & 31;
    const int n   = blockIdx.y;
    const int oh0 = blockIdx.x * 2;

    // k -> input offset table (floats): ic*4096 + kh*64 + kw
    for (int k = tid; k < KTOT; k += NTHR) {
        int ic = k / 9, t9 = k - ic * 9;
        int kh = t9 / 3, kw = t9 - kh * 3;
        offs[k] = ic * 4096 + kh * 64 + kw;
    }

    // A staging: per-thread row base (m = tid & 127), invalid ow clamped in-bounds
    const float* in_n = in + (size_t)n * 128 * 64 * 64;
    const int am = tid & 127, aib = tid >> 7;              // aib in 0..3
    const int aow = am & 63;
    const float* abase = in_n + (size_t)(oh0 + (am >> 6)) * 64 + (aow < 62 ? aow : 0);
    const int bq = tid & 7, bocb = tid >> 3;               // bocb in 0..63

    // warp tiling: 4x4 grid, warp tile m32 x n64
    const int m0 = (wid & 3) * 32, n0 = (wid >> 2) * 64;
    const int T = lane >> 3, rowin = lane & 7;
    uint32_t aoff[2], boff[4];
    #pragma unroll
    for (int mi = 0; mi < 2; mi++) {
        int r = m0 + mi * 16 + ((T & 1) << 3) + rowin;
        aoff[mi] = r * A_ROWB + ((T >> 1) << 4);
    }
    #pragma unroll
    for (int nb = 0; nb < 4; nb++) {
        int r = n0 + nb * 16 + ((T >> 1) << 3) + rowin;
        boff[nb] = r * B_ROWB + ((T & 1) << 4);
    }

    float acc[2][8][4];
    #pragma unroll
    for (int i = 0; i < 2; i++)
        #pragma unroll
        for (int j = 0; j < 8; j++)
            #pragma unroll
            for (int v = 0; v < 4; v++) acc[i][j][v] = 0.0f;

    __syncthreads();   // offs table ready

    // ---- stage chunk 0 ----
    {
        const int kc = 0;
        uint32_t As = sb + SM_A0, Bs = sb + SM_B0;
        #pragma unroll
        for (int i = 0; i < 8; i++) {
            int kk = i * 4 + aib;
            CP4(As + am * A_ROWB + kk * 4, abase + offs[kc * 32 + kk]);
        }
        #pragma unroll
        for (int j = 0; j < 4; j++) {
            int oc = j * 64 + bocb;
            CP16(Bs + oc * B_ROWB + bq * 16, wt + (size_t)oc * KTOT + kc * 32 + bq * 4);
        }
        CP_COMMIT();
    }

    #pragma unroll 1
    for (int kc = 0; kc < NCH; kc++) {
        if (kc + 1 < NCH) {   // stage next chunk into other buffer
            uint32_t As = sb + (((kc + 1) & 1) ? SM_A1 : SM_A0);
            uint32_t Bs = sb + (((kc + 1) & 1) ? SM_B1 : SM_B0);
            #pragma unroll
            for (int i = 0; i < 8; i++) {
                int kk = i * 4 + aib;
                CP4(As + am * A_ROWB + kk * 4, abase + offs[(kc + 1) * 32 + kk]);
            }
            #pragma unroll
            for (int j = 0; j < 4; j++) {
                int oc = j * 64 + bocb;
                CP16(Bs + oc * B_ROWB + bq * 16,
                     wt + (size_t)oc * KTOT + (kc + 1) * 32 + bq * 4);
            }
            CP_COMMIT();
            asm volatile("cp.async.wait_group 1;" ::: "memory");
        } else {
            asm volatile("cp.async.wait_group 0;" ::: "memory");
        }
        __syncthreads();   // chunk kc visible to all

        // ---- compute chunk kc ----
        uint32_t As = sb + ((kc & 1) ? SM_A1 : SM_A0);
        uint32_t Bs = sb + ((kc & 1) ? SM_B1 : SM_B0);
        #pragma unroll
        for (int s = 0; s < 4; s++) {
            uint32_t a[2][4], b[4][4];
            #pragma unroll
            for (int mi = 0; mi < 2; mi++) {
                ldsm4(a[mi], As + aoff[mi] + s * 32);
                #pragma unroll
                for (int v = 0; v < 4; v++) a[mi][v] = f2tf(a[mi][v]);
            }
            #pragma unroll
            for (int nb = 0; nb < 4; nb++) {
                ldsm4(b[nb], Bs + boff[nb] + s * 32);
                #pragma unroll
                for (int v = 0; v < 4; v++) b[nb][v] = f2tf(b[nb][v]);
            }
            #pragma unroll
            for (int mi = 0; mi < 2; mi++)
                #pragma unroll
                for (int nb = 0; nb < 4; nb++) {
                    mma8(acc[mi][2 * nb],     a[mi], &b[nb][0]);
                    mma8(acc[mi][2 * nb + 1], a[mi], &b[nb][2]);
                }
        }
        __syncthreads();   // compute done before buffer reuse
    }

    // ---- epilogue: smem transpose to [oc][m], coalesced stores ----
    const int eg = lane >> 2, ee = lane & 3;
    #pragma unroll 1
    for (int p = 0; p < 2; p++) {
        if ((n0 >> 7) == p) {
            #pragma unroll
            for (int mi = 0; mi < 2; mi++)
                #pragma unroll
                for (int nj = 0; nj < 8; nj++) {
                    int ocl = n0 - p * 128 + nj * 8 + 2 * ee;
                    int mm  = m0 + mi * 16 + eg;
                    smf[ocl * EPI_LD + mm]           = acc[mi][nj][0];
                    smf[(ocl + 1) * EPI_LD + mm]     = acc[mi][nj][1];
                    smf[ocl * EPI_LD + mm + 8]       = acc[mi][nj][2];
                    smf[(ocl + 1) * EPI_LD + mm + 8] = acc[mi][nj][3];
                }
        }
        __syncthreads();
        #pragma unroll 4
        for (int i = 0; i < 32; i++) {
            int idx = i * NTHR + tid;
            int mm = idx & 127, ocl = idx >> 7;
            int ow = mm & 63, oh = oh0 + (mm >> 6);
            if (ow < 62)
                out[((size_t)n * 256 + p * 128 + ocl) * 3844 + (size_t)oh * 62 + ow]
                    = smf[ocl * EPI_LD + mm];
        }
        __syncthreads();
    }
}

extern "C" void kernel_launch(void* const* d_in, const int* in_sizes, int n_in,
                              void* d_out, int out_size)
{
    const float* in = (const float*)d_in[0];   // [32,128,64,64]
    const float* wt = (const float*)d_in[1];   // [256,128,3,3]
    float* out = (float*)d_out;                // [32,256,62,62]

    cudaFuncSetAttribute(conv2d_tf32_mmasync,
                         cudaFuncAttributeMaxDynamicSharedMemorySize, SM_TOT);
    dim3 grid(31, 32);
    conv2d_tf32_mmasync<<<grid, NTHR, SM_TOT>>>(in, wt, out);
}

// round 4
// speedup vs baseline: 4.2250x; 1.0875x over previous
#include <cuda_runtime.h>
#include <cstdint>

#define NTHR 512
#define KTOT 1152
#define NCH  36          // K chunks of 32

// smem layout (bytes)
#define A_ROWB 144       // 128B data + 16B pad (conflict-free ldmatrix)
#define B_ROWB 144
#define SM_A0  0                       // 128 rows * 144
#define SM_A1  18432
#define SM_B0  36864                   // 256 rows * 144
#define SM_B1  73728
#define SM_OFF 110592                  // 1152 int offsets
#define SM_TOT 115200
#define EPI_LD 132                     // epilogue [128 oc][132 m] floats

// ---- tf32-preconverted scratch (device globals: allowed scratch) ----
__device__ float g_in_tf[32u * 128u * 64u * 64u];   // 67.1 MB
__device__ float g_wt_tf[256u * KTOT];              // 1.18 MB

__device__ __forceinline__ uint32_t s2u(const void* p) {
    uint32_t a;
    asm("{ .reg .u64 t; cvta.to.shared.u64 t, %1; cvt.u32.u64 %0, t; }" : "=r"(a) : "l"(p));
    return a;
}

__device__ __forceinline__ void ldsm4(uint32_t* r, uint32_t addr) {
    asm volatile("ldmatrix.sync.aligned.m8n8.x4.shared.b16 {%0,%1,%2,%3}, [%4];"
        : "=r"(r[0]), "=r"(r[1]), "=r"(r[2]), "=r"(r[3]) : "r"(addr));
}

__device__ __forceinline__ float f2tf(float f) {
    uint32_t o;
    asm("cvt.rna.tf32.f32 %0, %1;" : "=r"(o) : "f"(f));
    return __uint_as_float(o);
}

__device__ __forceinline__ void mma8(float* d, const uint32_t* a, const uint32_t* b) {
    asm volatile("mma.sync.aligned.m16n8k8.row.col.f32.tf32.tf32.f32 "
        "{%0,%1,%2,%3}, {%4,%5,%6,%7}, {%8,%9}, {%0,%1,%2,%3};"
        : "+f"(d[0]), "+f"(d[1]), "+f"(d[2]), "+f"(d[3])
        : "r"(a[0]), "r"(a[1]), "r"(a[2]), "r"(a[3]), "r"(b[0]), "r"(b[1]));
}

#define CP4(dst, src) \
    asm volatile("cp.async.ca.shared.global [%0], [%1], 4;"  :: "r"(dst), "l"(src) : "memory")
#define CP16(dst, src) \
    asm volatile("cp.async.cg.shared.global [%0], [%1], 16;" :: "r"(dst), "l"(src) : "memory")
#define CP_COMMIT() asm volatile("cp.async.commit_group;" ::: "memory")

// ---- prepass: f32 -> tf32 bit patterns, vectorized ----
__global__ __launch_bounds__(256) void cvt_in_kernel(const float4* __restrict__ src) {
    float4* dst = reinterpret_cast<float4*>(g_in_tf);
    const int n4 = (32 * 128 * 64 * 64) / 4;
    for (int i = blockIdx.x * blockDim.x + threadIdx.x; i < n4; i += gridDim.x * blockDim.x) {
        float4 v = src[i];
        v.x = f2tf(v.x); v.y = f2tf(v.y); v.z = f2tf(v.z); v.w = f2tf(v.w);
        dst[i] = v;
    }
}
__global__ __launch_bounds__(256) void cvt_wt_kernel(const float4* __restrict__ src) {
    float4* dst = reinterpret_cast<float4*>(g_wt_tf);
    const int n4 = (256 * KTOT) / 4;
    for (int i = blockIdx.x * blockDim.x + threadIdx.x; i < n4; i += gridDim.x * blockDim.x) {
        float4 v = src[i];
        v.x = f2tf(v.x); v.y = f2tf(v.y); v.z = f2tf(v.z); v.w = f2tf(v.w);
        dst[i] = v;
    }
}

__global__ __launch_bounds__(NTHR, 1)
void conv2d_tf32_mmasync(float* __restrict__ out)
{
    extern __shared__ char smem[];
    const uint32_t sb = s2u(smem);
    float* smf = (float*)smem;
    int* offs = (int*)(smem + SM_OFF);

    const int tid = threadIdx.x;
    const int wid = tid >> 5, lane = tid & 31;
    const int n   = blockIdx.y;
    const int oh0 = blockIdx.x * 2;

    // k -> input offset table (floats): ic*4096 + kh*64 + kw
    for (int k = tid; k < KTOT; k += NTHR) {
        int ic = k / 9, t9 = k - ic * 9;
        int kh = t9 / 3, kw = t9 - kh * 3;
        offs[k] = ic * 4096 + kh * 64 + kw;
    }

    // A staging: per-thread row base (m = tid & 127), invalid ow clamped in-bounds
    const float* in_n = g_in_tf + (size_t)n * 128 * 64 * 64;
    const float* wt   = g_wt_tf;
    const int am = tid & 127, aib = tid >> 7;              // aib in 0..3
    const int aow = am & 63;
    const float* abase = in_n + (size_t)(oh0 + (am >> 6)) * 64 + (aow < 62 ? aow : 0);
    const int bq = tid & 7, bocb = tid >> 3;               // bocb in 0..63

    // warp tiling: 4x4 grid, warp tile m32 x n64
    const int m0 = (wid & 3) * 32, n0 = (wid >> 2) * 64;
    const int T = lane >> 3, rowin = lane & 7;
    uint32_t aoff[2], boff[4];
    #pragma unroll
    for (int mi = 0; mi < 2; mi++) {
        int r = m0 + mi * 16 + ((T & 1) << 3) + rowin;
        aoff[mi] = r * A_ROWB + ((T >> 1) << 4);
    }
    #pragma unroll
    for (int nb = 0; nb < 4; nb++) {
        int r = n0 + nb * 16 + ((T >> 1) << 3) + rowin;
        boff[nb] = r * B_ROWB + ((T & 1) << 4);
    }

    float acc[2][8][4];
    #pragma unroll
    for (int i = 0; i < 2; i++)
        #pragma unroll
        for (int j = 0; j < 8; j++)
            #pragma unroll
            for (int v = 0; v < 4; v++) acc[i][j][v] = 0.0f;

    __syncthreads();   // offs table ready

    // ---- stage chunk 0 ----
    {
        uint32_t As = sb + SM_A0, Bs = sb + SM_B0;
        #pragma unroll
        for (int i = 0; i < 8; i++) {
            int kk = i * 4 + aib;
            CP4(As + am * A_ROWB + kk * 4, abase + offs[kk]);
        }
        #pragma unroll
        for (int j = 0; j < 4; j++) {
            int oc = j * 64 + bocb;
            CP16(Bs + oc * B_ROWB + bq * 16, wt + (size_t)oc * KTOT + bq * 4);
        }
        CP_COMMIT();
    }

    #pragma unroll 1
    for (int kc = 0; kc < NCH; kc++) {
        if (kc + 1 < NCH) {   // stage next chunk into other buffer
            uint32_t As = sb + (((kc + 1) & 1) ? SM_A1 : SM_A0);
            uint32_t Bs = sb + (((kc + 1) & 1) ? SM_B1 : SM_B0);
            #pragma unroll
            for (int i = 0; i < 8; i++) {
                int kk = i * 4 + aib;
                CP4(As + am * A_ROWB + kk * 4, abase + offs[(kc + 1) * 32 + kk]);
            }
            #pragma unroll
            for (int j = 0; j < 4; j++) {
                int oc = j * 64 + bocb;
                CP16(Bs + oc * B_ROWB + bq * 16,
                     wt + (size_t)oc * KTOT + (kc + 1) * 32 + bq * 4);
            }
            CP_COMMIT();
            asm volatile("cp.async.wait_group 1;" ::: "memory");
        } else {
            asm volatile("cp.async.wait_group 0;" ::: "memory");
        }
        __syncthreads();   // chunk kc visible to all

        // ---- compute chunk kc: pure ldmatrix + mma ----
        uint32_t As = sb + ((kc & 1) ? SM_A1 : SM_A0);
        uint32_t Bs = sb + ((kc & 1) ? SM_B1 : SM_B0);
        #pragma unroll
        for (int s = 0; s < 4; s++) {
            uint32_t a[2][4], b[4][4];
            #pragma unroll
            for (int mi = 0; mi < 2; mi++)
                ldsm4(a[mi], As + aoff[mi] + s * 32);
            #pragma unroll
            for (int nb = 0; nb < 4; nb++)
                ldsm4(b[nb], Bs + boff[nb] + s * 32);
            #pragma unroll
            for (int mi = 0; mi < 2; mi++)
                #pragma unroll
                for (int nb = 0; nb < 4; nb++) {
                    mma8(acc[mi][2 * nb],     a[mi], &b[nb][0]);
                    mma8(acc[mi][2 * nb + 1], a[mi], &b[nb][2]);
                }
        }
        __syncthreads();   // compute done before buffer reuse
    }

    // ---- epilogue: smem transpose to [oc][m], coalesced stores ----
    const int eg = lane >> 2, ee = lane & 3;
    #pragma unroll 1
    for (int p = 0; p < 2; p++) {
        if ((n0 >> 7) == p) {
            #pragma unroll
            for (int mi = 0; mi < 2; mi++)
                #pragma unroll
                for (int nj = 0; nj < 8; nj++) {
                    int ocl = n0 - p * 128 + nj * 8 + 2 * ee;
                    int mm  = m0 + mi * 16 + eg;
                    smf[ocl * EPI_LD + mm]           = acc[mi][nj][0];
                    smf[(ocl + 1) * EPI_LD + mm]     = acc[mi][nj][1];
                    smf[ocl * EPI_LD + mm + 8]       = acc[mi][nj][2];
                    smf[(ocl + 1) * EPI_LD + mm + 8] = acc[mi][nj][3];
                }
        }
        __syncthreads();
        #pragma unroll 4
        for (int i = 0; i < 32; i++) {
            int idx = i * NTHR + tid;
            int mm = idx & 127, ocl = idx >> 7;
            int ow = mm & 63, oh = oh0 + (mm >> 6);
            if (ow < 62)
                out[((size_t)n * 256 + p * 128 + ocl) * 3844 + (size_t)oh * 62 + ow]
                    = smf[ocl * EPI_LD + mm];
        }
        __syncthreads();
    }
}

extern "C" void kernel_launch(void* const* d_in, const int* in_sizes, int n_in,
                              void* d_out, int out_size)
{
    const float* in = (const float*)d_in[0];   // [32,128,64,64]
    const float* wt = (const float*)d_in[1];   // [256,128,3,3]
    float* out = (float*)d_out;                // [32,256,62,62]

    // prepass: convert input + weights to tf32 bit patterns
    cvt_in_kernel<<<2048, 256>>>(reinterpret_cast<const float4*>(in));
    cvt_wt_kernel<<<288, 256>>>(reinterpret_cast<const float4*>(wt));

    cudaFuncSetAttribute(conv2d_tf32_mmasync,
                         cudaFuncAttributeMaxDynamicSharedMemorySize, SM_TOT);
    dim3 grid(31, 32);
    conv2d_tf32_mmasync<<<grid, NTHR, SM_TOT>>>(out);
}